// round 9
// baseline (speedup 1.0000x reference)
#include <cuda_runtime.h>
#include <cuda_bf16.h>
#include <cstdint>

#define NTOK 8192
#define KDIM 512
#define DDIM 4096

#define BM 128
#define BD 128
#define BK 64
#define KITERS (KDIM / BK)   // 8
#define DT (DDIM / BD)       // 32
#define NT (NTOK / BM)       // 64
#define PSLOTS (DT * 4)      // 128

#define OFF_AH 0
#define OFF_BH 16384
#define OFF_A8 32768
#define OFF_B8 49152
#define STAGE_BYTES 65536
#define SMEM_TOTAL (2 * STAGE_BYTES)  // 131072

__device__ __align__(16) __nv_bfloat16 g_Fhi[NTOK * KDIM];
__device__ __align__(16) __nv_bfloat16 g_Flo[NTOK * KDIM];
__device__ __align__(16) __nv_bfloat16 g_Ethi[DDIM * KDIM];  // E^T hi: [d][k]
__device__ __align__(16) __nv_bfloat16 g_Etlo[DDIM * KDIM];
// fragment-direct fp8 operands:
// g_A8: [rowblock16 (512)][kchunk16 (32)][512 B]  (A' = [a8 | al8*2^9])
// g_B8: [dblock8   (512)][kchunk16 (32)][256 B]  (B' = [bl8*2^13 | b8*2^4])
__device__ __align__(16) unsigned char g_A8[(size_t)512 * 32 * 512];
__device__ __align__(16) unsigned char g_B8[(size_t)512 * 32 * 256];
__device__ float g_partial[(size_t)PSLOTS * NTOK];

__device__ __forceinline__ unsigned smem_u32(const void* p) {
    unsigned a;
    asm("{ .reg .u64 t; cvta.to.shared.u64 t, %1; cvt.u32.u64 %0, t; }" : "=r"(a) : "l"(p));
    return a;
}

#define CP16(s, g) \
    asm volatile("cp.async.cg.shared.global [%0], [%1], 16;" :: "r"(s), "l"(g) : "memory")
#define CP_COMMIT() asm volatile("cp.async.commit_group;" ::: "memory")
#define CP_WAIT0()  asm volatile("cp.async.wait_group 0;" ::: "memory")

#define LDSM4(R, addr)                                                        \
    asm volatile("ldmatrix.sync.aligned.m8n8.x4.shared.b16 {%0,%1,%2,%3}, [%4];" \
        : "=r"((R)[0]), "=r"((R)[1]), "=r"((R)[2]), "=r"((R)[3]) : "r"(addr))

#define LDS128(R, addr)                                                       \
    asm volatile("ld.shared.v4.b32 {%0,%1,%2,%3}, [%4];"                      \
        : "=r"((R)[0]), "=r"((R)[1]), "=r"((R)[2]), "=r"((R)[3]) : "r"(addr))

#define LDS64(R, addr)                                                        \
    asm volatile("ld.shared.v2.b32 {%0,%1}, [%2];"                            \
        : "=r"((R)[0]), "=r"((R)[1]) : "r"(addr))

#define MMA16(C, A, b0, b1)                                                   \
    asm volatile("mma.sync.aligned.m16n8k16.row.col.f32.bf16.bf16.f32 "       \
        "{%0,%1,%2,%3}, {%4,%5,%6,%7}, {%8,%9}, {%0,%1,%2,%3};"               \
        : "+f"((C)[0]), "+f"((C)[1]), "+f"((C)[2]), "+f"((C)[3])              \
        : "r"((A)[0]), "r"((A)[1]), "r"((A)[2]), "r"((A)[3]), "r"(b0), "r"(b1))

#define MMA8(C, A, b0, b1)                                                    \
    asm volatile("mma.sync.aligned.m16n8k32.row.col.f32.e4m3.e4m3.f32 "       \
        "{%0,%1,%2,%3}, {%4,%5,%6,%7}, {%8,%9}, {%0,%1,%2,%3};"               \
        : "+f"((C)[0]), "+f"((C)[1]), "+f"((C)[2]), "+f"((C)[3])              \
        : "r"((A)[0]), "r"((A)[1]), "r"((A)[2]), "r"((A)[3]), "r"(b0), "r"(b1))

__device__ __forceinline__ unsigned pack4_e4m3(float f0, float f1, float f2, float f3) {
    unsigned short lo, hi;
    asm("cvt.rn.satfinite.e4m3x2.f32 %0, %1, %2;" : "=h"(lo) : "f"(f1), "f"(f0));
    asm("cvt.rn.satfinite.e4m3x2.f32 %0, %1, %2;" : "=h"(hi) : "f"(f3), "f"(f2));
    return (unsigned)lo | ((unsigned)hi << 16);
}

// ---------------- prep: bf16 hi/lo splits ----------------
__global__ void split_f_kernel(const float* __restrict__ f) {
    int i = blockIdx.x * blockDim.x + threadIdx.x;
    if (i < NTOK * KDIM) {
        float x = f[i];
        __nv_bfloat16 h = __float2bfloat16(x);
        g_Fhi[i] = h;
        g_Flo[i] = __float2bfloat16(x - __bfloat162float(h));
    }
}

__global__ void split_e_t_kernel(const float* __restrict__ e) {  // e: [KDIM][DDIM]
    __shared__ float t[32][33];
    int d0 = blockIdx.x * 32, k0 = blockIdx.y * 32;
    int tx = threadIdx.x, ty = threadIdx.y;
#pragma unroll
    for (int i = ty; i < 32; i += 8)
        t[i][tx] = e[(size_t)(k0 + i) * DDIM + d0 + tx];
    __syncthreads();
#pragma unroll
    for (int i = ty; i < 32; i += 8) {
        float x = t[tx][i];  // E[k0+tx][d0+i]
        size_t o = (size_t)(d0 + i) * KDIM + k0 + tx;
        __nv_bfloat16 h = __float2bfloat16(x);
        g_Ethi[o] = h;
        g_Etlo[o] = __float2bfloat16(x - __bfloat162float(h));
    }
}

// ---------------- prep: fragment-direct fp8 packs ----------------
__global__ void pack_a8_kernel() {
    int w    = (blockIdx.x * blockDim.x + threadIdx.x) >> 5;  // 512*32 warps
    int lane = threadIdx.x & 31;
    int rB = w >> 5, c = w & 31;
    int row0 = rB * 16 + (lane >> 2);
    int k0   = c * 16 + (lane & 3) * 4;
    float h[2][4], l[2][4];
#pragma unroll
    for (int rr = 0; rr < 2; rr++) {
        int row = row0 + rr * 8;
#pragma unroll
        for (int j = 0; j < 4; j++) {
            h[rr][j] = __bfloat162float(g_Fhi[(size_t)row * KDIM + k0 + j]);
            l[rr][j] = __bfloat162float(g_Flo[(size_t)row * KDIM + k0 + j]) * 512.0f;  // 2^9
        }
    }
    uint4 v;
    v.x = pack4_e4m3(h[0][0], h[0][1], h[0][2], h[0][3]);  // a0: a8 row,   k0..3
    v.y = pack4_e4m3(h[1][0], h[1][1], h[1][2], h[1][3]);  // a1: a8 row+8
    v.z = pack4_e4m3(l[0][0], l[0][1], l[0][2], l[0][3]);  // a2: al8 row   (slots 16..31)
    v.w = pack4_e4m3(l[1][0], l[1][1], l[1][2], l[1][3]);  // a3: al8 row+8
    reinterpret_cast<uint4*>(g_A8)[(size_t)w * 32 + lane] = v;
}

__global__ void pack_b8_kernel() {
    int w    = (blockIdx.x * blockDim.x + threadIdx.x) >> 5;  // 512*32 warps
    int lane = threadIdx.x & 31;
    int cB = w >> 5, c = w & 31;
    int d  = cB * 8 + (lane >> 2);
    int k0 = c * 16 + (lane & 3) * 4;
    float lo[4], hi[4];
#pragma unroll
    for (int j = 0; j < 4; j++) {
        lo[j] = __bfloat162float(g_Etlo[(size_t)d * KDIM + k0 + j]) * 8192.0f;  // 2^13
        hi[j] = __bfloat162float(g_Ethi[(size_t)d * KDIM + k0 + j]) * 16.0f;    // 2^4
    }
    uint2 v;
    v.x = pack4_e4m3(lo[0], lo[1], lo[2], lo[3]);  // b0: bl8 (slots 0..15)
    v.y = pack4_e4m3(hi[0], hi[1], hi[2], hi[3]);  // b1: b8  (slots 16..31)
    reinterpret_cast<uint2*>(g_B8)[(size_t)w * 32 + lane] = v;
}

__global__ void reduce_kernel(float* __restrict__ out) {
    int n = blockIdx.x * blockDim.x + threadIdx.x;
    if (n < NTOK) {
        float s = 0.f;
#pragma unroll
        for (int i = 0; i < PSLOTS; i++) s += g_partial[(size_t)i * NTOK + n];
        out[n] = s;
    }
}

// ---------------- main: bf16 hh + fp8 cross GEMM + fused diagonal ----------------
// 256 threads: warps 2(m) x 4(d); warp tile 64x32. BK=64, 2-stage cp.async.
__global__ void __launch_bounds__(256, 1)
mm_diag_kernel(const float* __restrict__ wmat, const float* __restrict__ bvec) {
    extern __shared__ char smem[];
    const unsigned sb = smem_u32(smem);
    const int tid  = threadIdx.x;
    const int lane = tid & 31;
    const int wid  = tid >> 5;
    const int wm   = wid & 1;   // 2 warps over tokens (64 each)
    const int wn   = wid >> 1;  // 4 warps over d (32 each)
    const int dg0  = blockIdx.x * BD;
    const int n0   = blockIdx.y * BM;

    const char* gAh = (const char*)g_Fhi;
    const char* gBh = (const char*)g_Ethi;

    auto load_stage = [&](int it, int s) {
        unsigned base = sb + (unsigned)s * STAGE_BYTES;
#pragma unroll
        for (int t = tid; t < 1024; t += 256) {  // Ah bf16: 128 rows x 8 chunks
            int row = t >> 3, cs = t & 7;
            unsigned soff = (unsigned)(row * 128) + (unsigned)((cs ^ (row & 7)) << 4);
            size_t goff = ((size_t)(n0 + row) * KDIM + (size_t)it * BK + cs * 8) * 2;
            CP16(base + OFF_AH + soff, gAh + goff);
        }
#pragma unroll
        for (int t = tid; t < 1024; t += 256) {  // Bh bf16: 128 d-rows x 8 chunks
            int row = t >> 3, cs = t & 7;
            unsigned soff = (unsigned)(row * 128) + (unsigned)((cs ^ (row & 7)) << 4);
            size_t goff = ((size_t)(dg0 + row) * KDIM + (size_t)it * BK + cs * 8) * 2;
            CP16(base + OFF_BH + soff, gBh + goff);
        }
#pragma unroll
        for (int t = tid; t < 1024; t += 256) {  // A8: 8 rowblocks x 2KB contiguous
            int rB = t >> 7, inner = t & 127;
            size_t goff = ((size_t)((n0 >> 4) + rB)) * 16384 + (size_t)it * 2048 + inner * 16;
            CP16(base + OFF_A8 + (unsigned)t * 16, (const char*)g_A8 + goff);
        }
#pragma unroll
        for (int t = tid; t < 1024; t += 256) {  // B8: 16 dblocks x 1KB contiguous
            int cB = t >> 6, inner = t & 63;
            size_t goff = ((size_t)((dg0 >> 3) + cB)) * 8192 + (size_t)it * 1024 + inner * 16;
            CP16(base + OFF_B8 + (unsigned)t * 16, (const char*)g_B8 + goff);
        }
    };

    load_stage(0, 0);
    CP_COMMIT();

    // bf16 ldmatrix base offsets (kk=0); kk step -> XOR (kk<<5)
    unsigned offA[4], offB[2];
#pragma unroll
    for (int ma = 0; ma < 4; ma++) {
        int row = wm * 64 + ma * 16 + (lane & 15);
        int ch  = lane >> 4;
        offA[ma] = (unsigned)(row * 128) + (unsigned)((ch ^ (row & 7)) << 4);
    }
#pragma unroll
    for (int b = 0; b < 2; b++) {
        int row = wn * 32 + b * 16 + (lane & 15);
        int ch  = lane >> 4;
        offB[b] = (unsigned)(row * 128) + (unsigned)((ch ^ (row & 7)) << 4);
    }

    float c_hh[4][4][4], c_x[4][4][4];
#pragma unroll
    for (int i = 0; i < 4; i++)
#pragma unroll
        for (int j = 0; j < 4; j++)
#pragma unroll
            for (int r = 0; r < 4; r++) { c_hh[i][j][r] = 0.f; c_x[i][j][r] = 0.f; }

    for (int it = 0; it < KITERS; it++) {
        CP_WAIT0();
        __syncthreads();
        if (it + 1 < KITERS) load_stage(it + 1, (it + 1) & 1);
        CP_COMMIT();

        unsigned base = sb + (unsigned)(it & 1) * STAGE_BYTES;
#pragma unroll
        for (int kk = 0; kk < 4; kk++) {
            unsigned kx = (unsigned)(kk << 5);
            // ---- bf16 hh ----
            uint32_t Ah[4][4], Bh[2][4];
#pragma unroll
            for (int ma = 0; ma < 4; ma++) LDSM4(Ah[ma], base + OFF_AH + (offA[ma] ^ kx));
#pragma unroll
            for (int b = 0; b < 2; b++)    LDSM4(Bh[b],  base + OFF_BH + (offB[b] ^ kx));
#pragma unroll
            for (int ma = 0; ma < 4; ma++)
#pragma unroll
                for (int b = 0; b < 2; b++) {
                    MMA16(c_hh[ma][2 * b],     Ah[ma], Bh[b][0], Bh[b][2]);
                    MMA16(c_hh[ma][2 * b + 1], Ah[ma], Bh[b][1], Bh[b][3]);
                }
            // ---- fp8 cross (hl + lh fused in k32) ----
            uint32_t A8f[4][4], B8f[4][2];
#pragma unroll
            for (int ma = 0; ma < 4; ma++)
                LDS128(A8f[ma], base + OFF_A8 + (unsigned)(((wm * 4 + ma) * 4 + kk) * 512) + (unsigned)(lane * 16));
#pragma unroll
            for (int nb = 0; nb < 4; nb++)
                LDS64(B8f[nb], base + OFF_B8 + (unsigned)(((wn * 4 + nb) * 4 + kk) * 256) + (unsigned)(lane * 8));
#pragma unroll
            for (int ma = 0; ma < 4; ma++)
#pragma unroll
                for (int nb = 0; nb < 4; nb++)
                    MMA8(c_x[ma][nb], A8f[ma], B8f[nb][0], B8f[nb][1]);
        }
    }

    // ---- fused epilogue: partial[n] += sum_d (y + b[d]) * w[d][n] ----
    const float XS = 1.220703125e-4f;  // 2^-13
    const int g  = lane >> 2;
    const int cc = lane & 3;
    float rowacc[8];
#pragma unroll
    for (int ma = 0; ma < 4; ma++) {
#pragma unroll
        for (int rh = 0; rh < 2; rh++) {
            int n = n0 + wm * 64 + ma * 16 + g + rh * 8;
            float acc = 0.f;
#pragma unroll
            for (int j = 0; j < 4; j++) {
#pragma unroll
                for (int cb = 0; cb < 2; cb++) {
                    int d = dg0 + wn * 32 + j * 8 + cc * 2 + cb;
                    float y = c_hh[ma][j][rh * 2 + cb] + c_x[ma][j][rh * 2 + cb] * XS + __ldg(&bvec[d]);
                    acc = fmaf(y, __ldg(&wmat[(size_t)d * NTOK + n]), acc);
                }
            }
            rowacc[ma * 2 + rh] = acc;
        }
    }
#pragma unroll
    for (int i = 0; i < 8; i++) {
        rowacc[i] += __shfl_xor_sync(0xFFFFFFFFu, rowacc[i], 1);
        rowacc[i] += __shfl_xor_sync(0xFFFFFFFFu, rowacc[i], 2);
    }
    if (cc == 0) {
        int slot = blockIdx.x * 4 + wn;
#pragma unroll
        for (int ma = 0; ma < 4; ma++)
#pragma unroll
            for (int rh = 0; rh < 2; rh++) {
                int n = n0 + wm * 64 + ma * 16 + g + rh * 8;
                g_partial[(size_t)slot * NTOK + n] = rowacc[ma * 2 + rh];
            }
    }
}

// ---------------- launch ----------------
extern "C" void kernel_launch(void* const* d_in, const int* in_sizes, int n_in,
                              void* d_out, int out_size) {
    const float* features = (const float*)d_in[0];  // [8192, 512]
    const float* w        = (const float*)d_in[1];  // [4096, 8192]
    const float* E        = (const float*)d_in[2];  // [512, 4096]
    const float* b        = (const float*)d_in[3];  // [4096]
    float* out            = (float*)d_out;          // [8192]

    cudaFuncSetAttribute(mm_diag_kernel, cudaFuncAttributeMaxDynamicSharedMemorySize, SMEM_TOTAL);

    split_f_kernel<<<(NTOK * KDIM + 255) / 256, 256>>>(features);
    split_e_t_kernel<<<dim3(DDIM / 32, KDIM / 32), dim3(32, 8)>>>(E);
    pack_a8_kernel<<<2048, 256>>>();   // 512*32 warps
    pack_b8_kernel<<<2048, 256>>>();   // 512*32 warps
    mm_diag_kernel<<<dim3(DT, NT), 256, SMEM_TOTAL>>>(w, b);
    reduce_kernel<<<(NTOK + 255) / 256, 256>>>(out);
}

// round 10
// speedup vs baseline: 1.2523x; 1.2523x over previous
#include <cuda_runtime.h>
#include <cuda_bf16.h>
#include <cstdint>

#define NTOK 8192
#define KDIM 512
#define DDIM 4096

#define BM 128
#define BD 128
#define BK 64
#define KITERS (KDIM / BK)   // 8
#define DT (DDIM / BD)       // 32
#define NT (NTOK / BM)       // 64
#define PSLOTS (DT * 4)      // 128

#define ROWB 272             // 256B data + 16B pad (16B-aligned, conflict-free)
#define OFF_A 0
#define OFF_B 34816          // 128 * 272
#define STAGE_BYTES 69632
#define SMEM_TOTAL (2 * STAGE_BYTES)  // 139264

__device__ __align__(16) uint32_t g_Ft[NTOK * KDIM];   // tf32-rounded F
__device__ __align__(16) uint32_t g_Et[DDIM * KDIM];   // tf32-rounded E^T [d][k]
__device__ float g_partial[(size_t)PSLOTS * NTOK];

__device__ __forceinline__ unsigned smem_u32(const void* p) {
    unsigned a;
    asm("{ .reg .u64 t; cvta.to.shared.u64 t, %1; cvt.u32.u64 %0, t; }" : "=r"(a) : "l"(p));
    return a;
}
__device__ __forceinline__ uint32_t to_tf32(float x) {
    uint32_t r;
    asm("cvt.rna.tf32.f32 %0, %1;" : "=r"(r) : "f"(x));
    return r;
}

#define CP16(s, g) \
    asm volatile("cp.async.cg.shared.global [%0], [%1], 16;" :: "r"(s), "l"(g) : "memory")
#define CP_COMMIT() asm volatile("cp.async.commit_group;" ::: "memory")
#define CP_WAIT0()  asm volatile("cp.async.wait_group 0;" ::: "memory")

#define LDS32(r, addr) \
    asm volatile("ld.shared.b32 %0, [%1];" : "=r"(r) : "r"(addr))

#define MMAT(C, a0, a1, a2, a3, b0, b1)                                       \
    asm volatile("mma.sync.aligned.m16n8k8.row.col.f32.tf32.tf32.f32 "        \
        "{%0,%1,%2,%3}, {%4,%5,%6,%7}, {%8,%9}, {%0,%1,%2,%3};"               \
        : "+f"((C)[0]), "+f"((C)[1]), "+f"((C)[2]), "+f"((C)[3])              \
        : "r"(a0), "r"(a1), "r"(a2), "r"(a3), "r"(b0), "r"(b1))

// ---------------- prep ----------------
__global__ void round_f_kernel(const float* __restrict__ f) {
    int i = blockIdx.x * blockDim.x + threadIdx.x;
    if (i < NTOK * KDIM) g_Ft[i] = to_tf32(f[i]);
}

__global__ void round_e_t_kernel(const float* __restrict__ e) {  // e: [KDIM][DDIM]
    __shared__ float t[32][33];
    int d0 = blockIdx.x * 32, k0 = blockIdx.y * 32;
    int tx = threadIdx.x, ty = threadIdx.y;
#pragma unroll
    for (int i = ty; i < 32; i += 8)
        t[i][tx] = e[(size_t)(k0 + i) * DDIM + d0 + tx];
    __syncthreads();
#pragma unroll
    for (int i = ty; i < 32; i += 8)
        g_Et[(size_t)(d0 + i) * KDIM + k0 + tx] = to_tf32(t[tx][i]);
}

__global__ void reduce_kernel(float* __restrict__ out) {
    int n = blockIdx.x * blockDim.x + threadIdx.x;
    if (n < NTOK) {
        float s = 0.f;
#pragma unroll
        for (int i = 0; i < PSLOTS; i++) s += g_partial[(size_t)i * NTOK + n];
        out[n] = s;
    }
}

// ---------------- main: single-pass tf32 GEMM + fused diagonal ----------------
// 256 threads: warps 2(m) x 4(n); warp tile 64x32. BK=64, 2-stage cp.async.
__global__ void __launch_bounds__(256, 1)
mm_diag_kernel(const float* __restrict__ wmat, const float* __restrict__ bvec) {
    extern __shared__ char smem[];
    const unsigned sb = smem_u32(smem);
    const int tid  = threadIdx.x;
    const int lane = tid & 31;
    const int wid  = tid >> 5;
    const int wm   = wid & 1;   // 2 warps over tokens (64 each)
    const int wn   = wid >> 1;  // 4 warps over d (32 each)
    const int dg0  = blockIdx.x * BD;
    const int n0   = blockIdx.y * BM;
    const int g    = lane >> 2; // row-in-8
    const int cc   = lane & 3;  // k / col group

    const char* gA = (const char*)g_Ft;
    const char* gB = (const char*)g_Et;

    auto load_stage = [&](int it, int s) {
        unsigned base = sb + (unsigned)s * STAGE_BYTES;
#pragma unroll
        for (int t = tid; t < 2048; t += 256) {  // A: 128 rows x 16 chunks(16B)
            int row = t >> 4, cs = t & 15;
            unsigned soff = (unsigned)(row * ROWB + cs * 16);
            size_t goff = (size_t)(n0 + row) * (KDIM * 4) + (size_t)it * (BK * 4) + cs * 16;
            CP16(base + OFF_A + soff, gA + goff);
        }
#pragma unroll
        for (int t = tid; t < 2048; t += 256) {  // B: 128 d-rows x 16 chunks
            int row = t >> 4, cs = t & 15;
            unsigned soff = (unsigned)(row * ROWB + cs * 16);
            size_t goff = (size_t)(dg0 + row) * (KDIM * 4) + (size_t)it * (BK * 4) + cs * 16;
            CP16(base + OFF_B + soff, gB + goff);
        }
    };

    load_stage(0, 0);
    CP_COMMIT();

    // per-lane fragment byte offsets at kk=0; kk step adds 32B (8 floats)
    unsigned offA[4], offB[4];
#pragma unroll
    for (int ma = 0; ma < 4; ma++)
        offA[ma] = (unsigned)((wm * 64 + ma * 16 + g) * ROWB + cc * 4);
#pragma unroll
    for (int nb = 0; nb < 4; nb++)
        offB[nb] = (unsigned)((wn * 32 + nb * 8 + g) * ROWB + cc * 4);

    float c[4][4][4];
#pragma unroll
    for (int i = 0; i < 4; i++)
#pragma unroll
        for (int j = 0; j < 4; j++)
#pragma unroll
            for (int r = 0; r < 4; r++) c[i][j][r] = 0.f;

    for (int it = 0; it < KITERS; it++) {
        CP_WAIT0();
        __syncthreads();
        if (it + 1 < KITERS) load_stage(it + 1, (it + 1) & 1);
        CP_COMMIT();

        unsigned baseA = sb + (unsigned)(it & 1) * STAGE_BYTES + OFF_A;
        unsigned baseB = sb + (unsigned)(it & 1) * STAGE_BYTES + OFF_B;
#pragma unroll
        for (int kk = 0; kk < 8; kk++) {
            unsigned ko = (unsigned)(kk * 32);
            uint32_t a[4][4], b[4][2];
#pragma unroll
            for (int ma = 0; ma < 4; ma++) {
                unsigned ad = baseA + offA[ma] + ko;
                LDS32(a[ma][0], ad);               // (g,   c)
                LDS32(a[ma][1], ad + 8 * ROWB);    // (g+8, c)
                LDS32(a[ma][2], ad + 16);          // (g,   c+4)
                LDS32(a[ma][3], ad + 8 * ROWB + 16);
            }
#pragma unroll
            for (int nb = 0; nb < 4; nb++) {
                unsigned bd = baseB + offB[nb] + ko;
                LDS32(b[nb][0], bd);               // (n=g, k=c)
                LDS32(b[nb][1], bd + 16);          // (n=g, k=c+4)
            }
#pragma unroll
            for (int ma = 0; ma < 4; ma++)
#pragma unroll
                for (int nb = 0; nb < 4; nb++)
                    MMAT(c[ma][nb], a[ma][0], a[ma][1], a[ma][2], a[ma][3],
                         b[nb][0], b[nb][1]);
        }
    }

    // ---- fused epilogue: partial[n] += sum_d (y + b[d]) * w[d][n] ----
    float rowacc[8];
#pragma unroll
    for (int ma = 0; ma < 4; ma++) {
#pragma unroll
        for (int rh = 0; rh < 2; rh++) {
            int n = n0 + wm * 64 + ma * 16 + g + rh * 8;
            float acc = 0.f;
#pragma unroll
            for (int nb = 0; nb < 4; nb++) {
#pragma unroll
                for (int cb = 0; cb < 2; cb++) {
                    int d = dg0 + wn * 32 + nb * 8 + cc * 2 + cb;
                    float y = c[ma][nb][rh * 2 + cb] + __ldg(&bvec[d]);
                    acc = fmaf(y, __ldg(&wmat[(size_t)d * NTOK + n]), acc);
                }
            }
            rowacc[ma * 2 + rh] = acc;
        }
    }
#pragma unroll
    for (int i = 0; i < 8; i++) {
        rowacc[i] += __shfl_xor_sync(0xFFFFFFFFu, rowacc[i], 1);
        rowacc[i] += __shfl_xor_sync(0xFFFFFFFFu, rowacc[i], 2);
    }
    if (cc == 0) {
        int slot = blockIdx.x * 4 + wn;
#pragma unroll
        for (int ma = 0; ma < 4; ma++)
#pragma unroll
            for (int rh = 0; rh < 2; rh++) {
                int n = n0 + wm * 64 + ma * 16 + g + rh * 8;
                g_partial[(size_t)slot * NTOK + n] = rowacc[ma * 2 + rh];
            }
    }
}

// ---------------- launch ----------------
extern "C" void kernel_launch(void* const* d_in, const int* in_sizes, int n_in,
                              void* d_out, int out_size) {
    const float* features = (const float*)d_in[0];  // [8192, 512]
    const float* w        = (const float*)d_in[1];  // [4096, 8192]
    const float* E        = (const float*)d_in[2];  // [512, 4096]
    const float* b        = (const float*)d_in[3];  // [4096]
    float* out            = (float*)d_out;          // [8192]

    cudaFuncSetAttribute(mm_diag_kernel, cudaFuncAttributeMaxDynamicSharedMemorySize, SMEM_TOTAL);

    round_f_kernel<<<(NTOK * KDIM + 255) / 256, 256>>>(features);
    round_e_t_kernel<<<dim3(DDIM / 32, KDIM / 32), dim3(32, 8)>>>(E);
    mm_diag_kernel<<<dim3(DT, NT), 256, SMEM_TOTAL>>>(w, b);
    reduce_kernel<<<(NTOK + 255) / 256, 256>>>(out);
}

// round 12
// speedup vs baseline: 1.5071x; 1.2034x over previous
#include <cuda_runtime.h>
#include <cuda_bf16.h>
#include <cstdint>

#define NTOK 8192
#define KDIM 512
#define DDIM 4096

#define BM 128
#define BD 128
#define BK 32
#define KITERS (KDIM / BK)   // 16
#define DT (DDIM / BD)       // 32
#define NT (NTOK / BM)       // 64
#define PSLOTS (DT * 4)      // 128

#define ROWB 144             // 128B data + 16B pad; bank(row g)=4g -> conflict-free
#define OFF_A 0
#define OFF_B 18432          // 128 * 144
#define STAGE_BYTES 36864
#define STAGES 3
#define SMEM_TOTAL (STAGES * STAGE_BYTES)  // 110592 -> 2 CTAs/SM

__device__ __align__(16) uint32_t g_Ft[NTOK * KDIM];   // tf32-rounded F
__device__ __align__(16) uint32_t g_Et[DDIM * KDIM];   // tf32-rounded E^T [d][k]
__device__ float g_partial[(size_t)PSLOTS * NTOK];

__device__ __forceinline__ unsigned smem_u32(const void* p) {
    unsigned a;
    asm("{ .reg .u64 t; cvta.to.shared.u64 t, %1; cvt.u32.u64 %0, t; }" : "=r"(a) : "l"(p));
    return a;
}
__device__ __forceinline__ uint32_t to_tf32(float x) {
    uint32_t r;
    asm("cvt.rna.tf32.f32 %0, %1;" : "=r"(r) : "f"(x));
    return r;
}

#define CP16(s, g) \
    asm volatile("cp.async.cg.shared.global [%0], [%1], 16;" :: "r"(s), "l"(g) : "memory")
#define CP_COMMIT() asm volatile("cp.async.commit_group;" ::: "memory")
#define CP_WAIT1()  asm volatile("cp.async.wait_group 1;" ::: "memory")

#define LDS32(r, addr) \
    asm volatile("ld.shared.b32 %0, [%1];" : "=r"(r) : "r"(addr))

#define MMAT(C, a0, a1, a2, a3, b0, b1)                                       \
    asm volatile("mma.sync.aligned.m16n8k8.row.col.f32.tf32.tf32.f32 "        \
        "{%0,%1,%2,%3}, {%4,%5,%6,%7}, {%8,%9}, {%0,%1,%2,%3};"               \
        : "+f"((C)[0]), "+f"((C)[1]), "+f"((C)[2]), "+f"((C)[3])              \
        : "r"(a0), "r"(a1), "r"(a2), "r"(a3), "r"(b0), "r"(b1))

// ---------------- prep ----------------
__global__ void round_f_kernel(const float* __restrict__ f) {
    int i = blockIdx.x * blockDim.x + threadIdx.x;
    if (i < NTOK * KDIM) g_Ft[i] = to_tf32(f[i]);
}

__global__ void round_e_t_kernel(const float* __restrict__ e) {  // e: [KDIM][DDIM]
    __shared__ float t[32][33];
    int d0 = blockIdx.x * 32, k0 = blockIdx.y * 32;
    int tx = threadIdx.x, ty = threadIdx.y;
#pragma unroll
    for (int i = ty; i < 32; i += 8)
        t[i][tx] = e[(size_t)(k0 + i) * DDIM + d0 + tx];
    __syncthreads();
#pragma unroll
    for (int i = ty; i < 32; i += 8)
        g_Et[(size_t)(d0 + i) * KDIM + k0 + tx] = to_tf32(t[tx][i]);
}

__global__ void reduce_kernel(float* __restrict__ out) {
    int n = blockIdx.x * blockDim.x + threadIdx.x;
    if (n < NTOK) {
        float s = 0.f;
#pragma unroll
        for (int i = 0; i < PSLOTS; i++) s += g_partial[(size_t)i * NTOK + n];
        out[n] = s;
    }
}

// ---------------- main: tf32 GEMM + fused diagonal; 2 CTAs/SM ----------------
// Ring invariant: stage `it` lives in slot (it % 3). Prefetch at iter `it`
// fills slot ((it+2) % 3), which was consumed at iter it-1 (all warps past it
// via the top-of-loop barrier).
__global__ void __launch_bounds__(256, 2)
mm_diag_kernel(const float* __restrict__ wmat, const float* __restrict__ bvec) {
    extern __shared__ char smem[];
    const unsigned sb = smem_u32(smem);
    const int tid  = threadIdx.x;
    const int lane = tid & 31;
    const int wid  = tid >> 5;
    const int wm   = wid & 1;   // 2 warps over tokens (64 each)
    const int wn   = wid >> 1;  // 4 warps over d (32 each)
    const int dg0  = blockIdx.x * BD;
    const int n0   = blockIdx.y * BM;
    const int g    = lane >> 2; // row-in-8
    const int cc   = lane & 3;  // k/col group

    const char* gA = (const char*)g_Ft;
    const char* gB = (const char*)g_Et;

    auto load_stage = [&](int it, int s) {
        unsigned base = sb + (unsigned)s * STAGE_BYTES;
#pragma unroll
        for (int t = tid; t < 1024; t += 256) {  // A: 128 rows x 8 chunks(16B)
            int row = t >> 3, cs = t & 7;
            unsigned soff = (unsigned)(row * ROWB + cs * 16);
            size_t goff = (size_t)(n0 + row) * (KDIM * 4) + (size_t)it * (BK * 4) + cs * 16;
            CP16(base + OFF_A + soff, gA + goff);
        }
#pragma unroll
        for (int t = tid; t < 1024; t += 256) {  // B: 128 d-rows x 8 chunks
            int row = t >> 3, cs = t & 7;
            unsigned soff = (unsigned)(row * ROWB + cs * 16);
            size_t goff = (size_t)(dg0 + row) * (KDIM * 4) + (size_t)it * (BK * 4) + cs * 16;
            CP16(base + OFF_B + soff, gB + goff);
        }
    };

    load_stage(0, 0); CP_COMMIT();
    load_stage(1, 1); CP_COMMIT();

    // per-lane fragment byte offsets (kk=0); kk step adds 32B
    unsigned offA[4], offB[4];
#pragma unroll
    for (int ma = 0; ma < 4; ma++)
        offA[ma] = (unsigned)((wm * 64 + ma * 16 + g) * ROWB + cc * 4);
#pragma unroll
    for (int nb = 0; nb < 4; nb++)
        offB[nb] = (unsigned)((wn * 32 + nb * 8 + g) * ROWB + cc * 4);

    float c[4][4][4];
#pragma unroll
    for (int i = 0; i < 4; i++)
#pragma unroll
        for (int j = 0; j < 4; j++)
#pragma unroll
            for (int r = 0; r < 4; r++) c[i][j][r] = 0.f;

    for (int it = 0; it < KITERS; it++) {
        CP_WAIT1();          // stage `it` resident (newest may be in flight)
        __syncthreads();     // everyone past slot ((it+2)%3)'s last read
        int slot = it % STAGES;
        unsigned baseA = sb + (unsigned)slot * STAGE_BYTES + OFF_A;
        unsigned baseB = sb + (unsigned)slot * STAGE_BYTES + OFF_B;

#pragma unroll
        for (int kk = 0; kk < 4; kk++) {
            unsigned ko = (unsigned)(kk * 32);
            uint32_t a[4][4], b[4][2];
#pragma unroll
            for (int ma = 0; ma < 4; ma++) {
                unsigned ad = baseA + offA[ma] + ko;
                LDS32(a[ma][0], ad);
                LDS32(a[ma][1], ad + 8 * ROWB);
                LDS32(a[ma][2], ad + 16);
                LDS32(a[ma][3], ad + 8 * ROWB + 16);
            }
#pragma unroll
            for (int nb = 0; nb < 4; nb++) {
                unsigned bd = baseB + offB[nb] + ko;
                LDS32(b[nb][0], bd);
                LDS32(b[nb][1], bd + 16);
            }
#pragma unroll
            for (int ma = 0; ma < 4; ma++)
#pragma unroll
                for (int nb = 0; nb < 4; nb++)
                    MMAT(c[ma][nb], a[ma][0], a[ma][1], a[ma][2], a[ma][3],
                         b[nb][0], b[nb][1]);
        }

        if (it + 2 < KITERS) {
            load_stage(it + 2, (it + 2) % STAGES);
            CP_COMMIT();
        }
    }

    // ---- fused epilogue: partial[n] += sum_d (y + b[d]) * w[d][n] ----
    float rowacc[8];
#pragma unroll
    for (int ma = 0; ma < 4; ma++) {
#pragma unroll
        for (int rh = 0; rh < 2; rh++) {
            int n = n0 + wm * 64 + ma * 16 + g + rh * 8;
            float acc = 0.f;
#pragma unroll
            for (int nb = 0; nb < 4; nb++) {
#pragma unroll
                for (int cb = 0; cb < 2; cb++) {
                    int d = dg0 + wn * 32 + nb * 8 + cc * 2 + cb;
                    float y = c[ma][nb][rh * 2 + cb] + __ldg(&bvec[d]);
                    acc = fmaf(y, __ldg(&wmat[(size_t)d * NTOK + n]), acc);
                }
            }
            rowacc[ma * 2 + rh] = acc;
        }
    }
#pragma unroll
    for (int i = 0; i < 8; i++) {
        rowacc[i] += __shfl_xor_sync(0xFFFFFFFFu, rowacc[i], 1);
        rowacc[i] += __shfl_xor_sync(0xFFFFFFFFu, rowacc[i], 2);
    }
    if (cc == 0) {
        int slot = blockIdx.x * 4 + wn;
#pragma unroll
        for (int ma = 0; ma < 4; ma++)
#pragma unroll
            for (int rh = 0; rh < 2; rh++) {
                int n = n0 + wm * 64 + ma * 16 + g + rh * 8;
                g_partial[(size_t)slot * NTOK + n] = rowacc[ma * 2 + rh];
            }
    }
}

// ---------------- launch ----------------
extern "C" void kernel_launch(void* const* d_in, const int* in_sizes, int n_in,
                              void* d_out, int out_size) {
    const float* features = (const float*)d_in[0];  // [8192, 512]
    const float* w        = (const float*)d_in[1];  // [4096, 8192]
    const float* E        = (const float*)d_in[2];  // [512, 4096]
    const float* b        = (const float*)d_in[3];  // [4096]
    float* out            = (float*)d_out;          // [8192]

    cudaFuncSetAttribute(mm_diag_kernel, cudaFuncAttributeMaxDynamicSharedMemorySize, SMEM_TOTAL);

    round_f_kernel<<<(NTOK * KDIM + 255) / 256, 256>>>(features);
    round_e_t_kernel<<<dim3(DDIM / 32, KDIM / 32), dim3(32, 8)>>>(E);
    mm_diag_kernel<<<dim3(DT, NT), 256, SMEM_TOTAL>>>(w, b);
    reduce_kernel<<<(NTOK + 255) / 256, 256>>>(out);
}

// round 13
// speedup vs baseline: 2.6864x; 1.7826x over previous
#include <cuda_runtime.h>
#include <cuda_fp16.h>
#include <cstdint>

#define NTOK 8192
#define KDIM 512
#define DDIM 4096

#define BM 128
#define BD 128
#define BK 64
#define KITERS (KDIM / BK)   // 8
#define DT (DDIM / BD)       // 32
#define NT (NTOK / BM)       // 64
#define PSLOTS (DT * 4)      // 128

#define OFF_A 0
#define OFF_B 16384
#define STAGE_BYTES 32768
#define STAGES 3
#define SMEM_TOTAL (STAGES * STAGE_BYTES)  // 98304 -> 2 CTAs/SM

__device__ __align__(16) __half g_Fh[NTOK * KDIM];   // fp16 F
__device__ __align__(16) __half g_Eh[DDIM * KDIM];   // fp16 E^T [d][k]
__device__ float g_partial[(size_t)PSLOTS * NTOK];

__device__ __forceinline__ unsigned smem_u32(const void* p) {
    unsigned a;
    asm("{ .reg .u64 t; cvta.to.shared.u64 t, %1; cvt.u32.u64 %0, t; }" : "=r"(a) : "l"(p));
    return a;
}

#define CP16(s, g) \
    asm volatile("cp.async.cg.shared.global [%0], [%1], 16;" :: "r"(s), "l"(g) : "memory")
#define CP_COMMIT() asm volatile("cp.async.commit_group;" ::: "memory")
#define CP_WAIT1()  asm volatile("cp.async.wait_group 1;" ::: "memory")

#define LDSM4(R, addr)                                                        \
    asm volatile("ldmatrix.sync.aligned.m8n8.x4.shared.b16 {%0,%1,%2,%3}, [%4];" \
        : "=r"((R)[0]), "=r"((R)[1]), "=r"((R)[2]), "=r"((R)[3]) : "r"(addr))

#define MMAH(C, A, b0, b1)                                                    \
    asm volatile("mma.sync.aligned.m16n8k16.row.col.f32.f16.f16.f32 "         \
        "{%0,%1,%2,%3}, {%4,%5,%6,%7}, {%8,%9}, {%0,%1,%2,%3};"               \
        : "+f"((C)[0]), "+f"((C)[1]), "+f"((C)[2]), "+f"((C)[3])              \
        : "r"((A)[0]), "r"((A)[1]), "r"((A)[2]), "r"((A)[3]), "r"(b0), "r"(b1))

// ---------------- prep ----------------
__global__ void conv_f_kernel(const float* __restrict__ f) {
    int i = blockIdx.x * blockDim.x + threadIdx.x;
    if (i < NTOK * KDIM) g_Fh[i] = __float2half(f[i]);
}

__global__ void conv_e_t_kernel(const float* __restrict__ e) {  // e: [KDIM][DDIM]
    __shared__ float t[32][33];
    int d0 = blockIdx.x * 32, k0 = blockIdx.y * 32;
    int tx = threadIdx.x, ty = threadIdx.y;
#pragma unroll
    for (int i = ty; i < 32; i += 8)
        t[i][tx] = e[(size_t)(k0 + i) * DDIM + d0 + tx];
    __syncthreads();
#pragma unroll
    for (int i = ty; i < 32; i += 8)
        g_Eh[(size_t)(d0 + i) * KDIM + k0 + tx] = __float2half(t[tx][i]);
}

__global__ void reduce_kernel(float* __restrict__ out) {
    int n = blockIdx.x * blockDim.x + threadIdx.x;
    if (n < NTOK) {
        float s = 0.f;
#pragma unroll
        for (int i = 0; i < PSLOTS; i++) s += g_partial[(size_t)i * NTOK + n];
        out[n] = s;
    }
}

// ---------------- main: single-pass fp16 GEMM + fused diagonal; 2 CTAs/SM ----
// Ring invariant: stage `it` lives in slot (it % 3); prefetch at iter `it`
// fills slot ((it+2) % 3), consumed at iter it-1 (top-of-loop barrier).
__global__ void __launch_bounds__(256, 2)
mm_diag_kernel(const float* __restrict__ wmat, const float* __restrict__ bvec) {
    extern __shared__ char smem[];
    const unsigned sb = smem_u32(smem);
    const int tid  = threadIdx.x;
    const int lane = tid & 31;
    const int wid  = tid >> 5;
    const int wm   = wid & 1;   // 2 warps over tokens (64 each)
    const int wn   = wid >> 1;  // 4 warps over d (32 each)
    const int dg0  = blockIdx.x * BD;
    const int n0   = blockIdx.y * BM;
    const int g    = lane >> 2;
    const int cc   = lane & 3;

    const char* gA = (const char*)g_Fh;
    const char* gB = (const char*)g_Eh;

    // rows are 128B (64 halfs = one BK chunk); swizzle: chunk ^= (row & 7)
    auto load_stage = [&](int it, int s) {
        unsigned base = sb + (unsigned)s * STAGE_BYTES;
#pragma unroll
        for (int t = tid; t < 1024; t += 256) {  // A: 128 rows x 8 chunks(16B)
            int row = t >> 3, cs = t & 7;
            unsigned soff = (unsigned)(row * 128) + (unsigned)((cs ^ (row & 7)) << 4);
            size_t goff = ((size_t)(n0 + row) * KDIM + (size_t)it * BK + cs * 8) * 2;
            CP16(base + OFF_A + soff, gA + goff);
        }
#pragma unroll
        for (int t = tid; t < 1024; t += 256) {  // B: 128 d-rows x 8 chunks
            int row = t >> 3, cs = t & 7;
            unsigned soff = (unsigned)(row * 128) + (unsigned)((cs ^ (row & 7)) << 4);
            size_t goff = ((size_t)(dg0 + row) * KDIM + (size_t)it * BK + cs * 8) * 2;
            CP16(base + OFF_B + soff, gB + goff);
        }
    };

    load_stage(0, 0); CP_COMMIT();
    load_stage(1, 1); CP_COMMIT();

    // ldmatrix base offsets (kk=0); kk step -> XOR (kk<<5)
    unsigned offA[4], offB[2];
#pragma unroll
    for (int ma = 0; ma < 4; ma++) {
        int row = wm * 64 + ma * 16 + (lane & 15);
        int ch  = lane >> 4;
        offA[ma] = (unsigned)(row * 128) + (unsigned)((ch ^ (row & 7)) << 4);
    }
#pragma unroll
    for (int b = 0; b < 2; b++) {
        int row = wn * 32 + b * 16 + (lane & 15);
        int ch  = lane >> 4;
        offB[b] = (unsigned)(row * 128) + (unsigned)((ch ^ (row & 7)) << 4);
    }

    float c[4][4][4];
#pragma unroll
    for (int i = 0; i < 4; i++)
#pragma unroll
        for (int j = 0; j < 4; j++)
#pragma unroll
            for (int r = 0; r < 4; r++) c[i][j][r] = 0.f;

    for (int it = 0; it < KITERS; it++) {
        CP_WAIT1();          // stage `it` resident (newest may be in flight)
        __syncthreads();
        int slot = it % STAGES;
        unsigned baseA = sb + (unsigned)slot * STAGE_BYTES + OFF_A;
        unsigned baseB = sb + (unsigned)slot * STAGE_BYTES + OFF_B;

#pragma unroll
        for (int kk = 0; kk < 4; kk++) {
            unsigned kx = (unsigned)(kk << 5);
            uint32_t Ah[4][4], Bh[2][4];
#pragma unroll
            for (int ma = 0; ma < 4; ma++) LDSM4(Ah[ma], baseA + (offA[ma] ^ kx));
#pragma unroll
            for (int b = 0; b < 2; b++)    LDSM4(Bh[b],  baseB + (offB[b] ^ kx));
#pragma unroll
            for (int ma = 0; ma < 4; ma++)
#pragma unroll
                for (int b = 0; b < 2; b++) {
                    MMAH(c[ma][2 * b],     Ah[ma], Bh[b][0], Bh[b][2]);
                    MMAH(c[ma][2 * b + 1], Ah[ma], Bh[b][1], Bh[b][3]);
                }
        }

        if (it + 2 < KITERS) {
            load_stage(it + 2, (it + 2) % STAGES);
            CP_COMMIT();
        }
    }

    // ---- fused epilogue: partial[n] += sum_d (y + b[d]) * w[d][n] ----
    float rowacc[8];
#pragma unroll
    for (int ma = 0; ma < 4; ma++) {
#pragma unroll
        for (int rh = 0; rh < 2; rh++) {
            int n = n0 + wm * 64 + ma * 16 + g + rh * 8;
            float acc = 0.f;
#pragma unroll
            for (int nb = 0; nb < 4; nb++) {
#pragma unroll
                for (int cb = 0; cb < 2; cb++) {
                    int d = dg0 + wn * 32 + nb * 8 + cc * 2 + cb;
                    float y = c[ma][nb][rh * 2 + cb] + __ldg(&bvec[d]);
                    acc = fmaf(y, __ldg(&wmat[(size_t)d * NTOK + n]), acc);
                }
            }
            rowacc[ma * 2 + rh] = acc;
        }
    }
#pragma unroll
    for (int i = 0; i < 8; i++) {
        rowacc[i] += __shfl_xor_sync(0xFFFFFFFFu, rowacc[i], 1);
        rowacc[i] += __shfl_xor_sync(0xFFFFFFFFu, rowacc[i], 2);
    }
    if (cc == 0) {
        int slot = blockIdx.x * 4 + wn;
#pragma unroll
        for (int ma = 0; ma < 4; ma++)
#pragma unroll
            for (int rh = 0; rh < 2; rh++) {
                int n = n0 + wm * 64 + ma * 16 + g + rh * 8;
                g_partial[(size_t)slot * NTOK + n] = rowacc[ma * 2 + rh];
            }
    }
}

// ---------------- launch ----------------
extern "C" void kernel_launch(void* const* d_in, const int* in_sizes, int n_in,
                              void* d_out, int out_size) {
    const float* features = (const float*)d_in[0];  // [8192, 512]
    const float* w        = (const float*)d_in[1];  // [4096, 8192]
    const float* E        = (const float*)d_in[2];  // [512, 4096]
    const float* b        = (const float*)d_in[3];  // [4096]
    float* out            = (float*)d_out;          // [8192]

    cudaFuncSetAttribute(mm_diag_kernel, cudaFuncAttributeMaxDynamicSharedMemorySize, SMEM_TOTAL);

    conv_f_kernel<<<(NTOK * KDIM + 255) / 256, 256>>>(features);
    conv_e_t_kernel<<<dim3(DDIM / 32, KDIM / 32), dim3(32, 8)>>>(E);
    mm_diag_kernel<<<dim3(DT, NT), 256, SMEM_TOTAL>>>(w, b);
    reduce_kernel<<<(NTOK + 255) / 256, 256>>>(out);
}

// round 14
// speedup vs baseline: 2.6884x; 1.0007x over previous
#include <cuda_runtime.h>
#include <cuda_fp16.h>
#include <cstdint>

#define NTOK 8192
#define KDIM 512
#define DDIM 4096

#define BM 128
#define BD 128
#define BK 64
#define KITERS (KDIM / BK)   // 8
#define DT (DDIM / BD)       // 32
#define NT (NTOK / BM)       // 64
#define PSLOTS DT            // 32 (wn reduced inside CTA)

#define OFF_A 0
#define OFF_B 16384
#define STAGE_BYTES 32768
#define STAGES 3
#define SMEM_TOTAL (STAGES * STAGE_BYTES)  // 98304 -> 2 CTAs/SM

__device__ __align__(16) __half g_Fh[NTOK * KDIM];   // fp16 F
__device__ __align__(16) __half g_Eh[DDIM * KDIM];   // fp16 E^T [d][k]
__device__ float g_partial[(size_t)PSLOTS * NTOK];

__device__ __forceinline__ unsigned smem_u32(const void* p) {
    unsigned a;
    asm("{ .reg .u64 t; cvta.to.shared.u64 t, %1; cvt.u32.u64 %0, t; }" : "=r"(a) : "l"(p));
    return a;
}

#define CP16(s, g) \
    asm volatile("cp.async.cg.shared.global [%0], [%1], 16;" :: "r"(s), "l"(g) : "memory")
#define CP_COMMIT() asm volatile("cp.async.commit_group;" ::: "memory")
#define CP_WAIT1()  asm volatile("cp.async.wait_group 1;" ::: "memory")
#define CP_WAIT0()  asm volatile("cp.async.wait_group 0;" ::: "memory")

#define LDSM4(R, addr)                                                        \
    asm volatile("ldmatrix.sync.aligned.m8n8.x4.shared.b16 {%0,%1,%2,%3}, [%4];" \
        : "=r"((R)[0]), "=r"((R)[1]), "=r"((R)[2]), "=r"((R)[3]) : "r"(addr))

#define MMAH(C, A, b0, b1)                                                    \
    asm volatile("mma.sync.aligned.m16n8k16.row.col.f32.f16.f16.f32 "         \
        "{%0,%1,%2,%3}, {%4,%5,%6,%7}, {%8,%9}, {%0,%1,%2,%3};"               \
        : "+f"((C)[0]), "+f"((C)[1]), "+f"((C)[2]), "+f"((C)[3])              \
        : "r"((A)[0]), "r"((A)[1]), "r"((A)[2]), "r"((A)[3]), "r"(b0), "r"(b1))

// ---------------- prep ----------------
__global__ void conv_f_kernel(const float* __restrict__ f) {
    int i = blockIdx.x * blockDim.x + threadIdx.x;
    if (i < NTOK * KDIM) g_Fh[i] = __float2half(f[i]);
}

__global__ void conv_e_t_kernel(const float* __restrict__ e) {  // e: [KDIM][DDIM]
    __shared__ float t[32][33];
    int d0 = blockIdx.x * 32, k0 = blockIdx.y * 32;
    int tx = threadIdx.x, ty = threadIdx.y;
#pragma unroll
    for (int i = ty; i < 32; i += 8)
        t[i][tx] = e[(size_t)(k0 + i) * DDIM + d0 + tx];
    __syncthreads();
#pragma unroll
    for (int i = ty; i < 32; i += 8)
        g_Eh[(size_t)(d0 + i) * KDIM + k0 + tx] = __float2half(t[tx][i]);
}

__global__ void reduce_kernel(float* __restrict__ out) {
    int n = blockIdx.x * blockDim.x + threadIdx.x;
    if (n < NTOK) {
        float s = 0.f;
#pragma unroll
        for (int i = 0; i < PSLOTS; i++) s += g_partial[(size_t)i * NTOK + n];
        out[n] = s;
    }
}

// ---------------- main: single-pass fp16 GEMM + fused diagonal; 2 CTAs/SM ----
// Ring invariant: stage `it` lives in slot (it % 3); prefetch at iter `it`
// fills slot ((it+2) % 3), consumed at iter it-1 (top-of-loop barrier).
// Last iteration drains ALL cp.async groups (its own stage's group can be
// the newest in-flight one — wait_group 1 would not cover it).
__global__ void __launch_bounds__(256, 2)
mm_diag_kernel(const float* __restrict__ wmat, const float* __restrict__ bvec) {
    extern __shared__ char smem[];
    const unsigned sb = smem_u32(smem);
    const int tid  = threadIdx.x;
    const int lane = tid & 31;
    const int wid  = tid >> 5;
    const int wm   = wid & 1;   // 2 warps over tokens (64 each)
    const int wn   = wid >> 1;  // 4 warps over d (32 each)
    const int dg0  = blockIdx.x * BD;
    const int n0   = blockIdx.y * BM;
    const int g    = lane >> 2;
    const int cc   = lane & 3;

    const char* gA = (const char*)g_Fh;
    const char* gB = (const char*)g_Eh;

    // rows are 128B (64 halfs = one BK chunk); swizzle: chunk ^= (row & 7)
    auto load_stage = [&](int it, int s) {
        unsigned base = sb + (unsigned)s * STAGE_BYTES;
#pragma unroll
        for (int t = tid; t < 1024; t += 256) {  // A: 128 rows x 8 chunks(16B)
            int row = t >> 3, cs = t & 7;
            unsigned soff = (unsigned)(row * 128) + (unsigned)((cs ^ (row & 7)) << 4);
            size_t goff = ((size_t)(n0 + row) * KDIM + (size_t)it * BK + cs * 8) * 2;
            CP16(base + OFF_A + soff, gA + goff);
        }
#pragma unroll
        for (int t = tid; t < 1024; t += 256) {  // B: 128 d-rows x 8 chunks
            int row = t >> 3, cs = t & 7;
            unsigned soff = (unsigned)(row * 128) + (unsigned)((cs ^ (row & 7)) << 4);
            size_t goff = ((size_t)(dg0 + row) * KDIM + (size_t)it * BK + cs * 8) * 2;
            CP16(base + OFF_B + soff, gB + goff);
        }
    };

    load_stage(0, 0); CP_COMMIT();
    load_stage(1, 1); CP_COMMIT();

    // ldmatrix base offsets (kk=0); kk step -> XOR (kk<<5)
    unsigned offA[4], offB[2];
#pragma unroll
    for (int ma = 0; ma < 4; ma++) {
        int row = wm * 64 + ma * 16 + (lane & 15);
        int ch  = lane >> 4;
        offA[ma] = (unsigned)(row * 128) + (unsigned)((ch ^ (row & 7)) << 4);
    }
#pragma unroll
    for (int b = 0; b < 2; b++) {
        int row = wn * 32 + b * 16 + (lane & 15);
        int ch  = lane >> 4;
        offB[b] = (unsigned)(row * 128) + (unsigned)((ch ^ (row & 7)) << 4);
    }

    float c[4][4][4];
#pragma unroll
    for (int i = 0; i < 4; i++)
#pragma unroll
        for (int j = 0; j < 4; j++)
#pragma unroll
            for (int r = 0; r < 4; r++) c[i][j][r] = 0.f;

    for (int it = 0; it < KITERS; it++) {
        if (it == KITERS - 1) { CP_WAIT0(); } else { CP_WAIT1(); }
        __syncthreads();
        int slot = it % STAGES;
        unsigned baseA = sb + (unsigned)slot * STAGE_BYTES + OFF_A;
        unsigned baseB = sb + (unsigned)slot * STAGE_BYTES + OFF_B;

#pragma unroll
        for (int kk = 0; kk < 4; kk++) {
            unsigned kx = (unsigned)(kk << 5);
            uint32_t Ah[4][4], Bh[2][4];
#pragma unroll
            for (int ma = 0; ma < 4; ma++) LDSM4(Ah[ma], baseA + (offA[ma] ^ kx));
#pragma unroll
            for (int b = 0; b < 2; b++)    LDSM4(Bh[b],  baseB + (offB[b] ^ kx));
#pragma unroll
            for (int ma = 0; ma < 4; ma++)
#pragma unroll
                for (int b = 0; b < 2; b++) {
                    MMAH(c[ma][2 * b],     Ah[ma], Bh[b][0], Bh[b][2]);
                    MMAH(c[ma][2 * b + 1], Ah[ma], Bh[b][1], Bh[b][3]);
                }
        }

        if (it + 2 < KITERS) {
            load_stage(it + 2, (it + 2) % STAGES);
            CP_COMMIT();
        }
    }

    // ---- fused epilogue: partial[n] += sum_d (y + b[d]) * w[d][n] ----
    float rowacc[8];
#pragma unroll
    for (int ma = 0; ma < 4; ma++) {
#pragma unroll
        for (int rh = 0; rh < 2; rh++) {
            int n = n0 + wm * 64 + ma * 16 + g + rh * 8;
            float acc = 0.f;
#pragma unroll
            for (int nb = 0; nb < 4; nb++) {
#pragma unroll
                for (int cb = 0; cb < 2; cb++) {
                    int d = dg0 + wn * 32 + nb * 8 + cc * 2 + cb;
                    float y = c[ma][nb][rh * 2 + cb] + __ldg(&bvec[d]);
                    acc = fmaf(y, __ldg(&wmat[(size_t)d * NTOK + n]), acc);
                }
            }
            rowacc[ma * 2 + rh] = acc;
        }
    }
#pragma unroll
    for (int i = 0; i < 8; i++) {
        rowacc[i] += __shfl_xor_sync(0xFFFFFFFFu, rowacc[i], 1);
        rowacc[i] += __shfl_xor_sync(0xFFFFFFFFu, rowacc[i], 2);
    }

    // ---- intra-CTA reduction over wn (4 slices) via smem; one slot per CTA-x
    __syncthreads();  // all warps done reading pipeline smem
    float* red = reinterpret_cast<float*>(smem);  // [4][128]
    if (cc == 0) {
#pragma unroll
        for (int ma = 0; ma < 4; ma++)
#pragma unroll
            for (int rh = 0; rh < 2; rh++) {
                int nloc = wm * 64 + ma * 16 + g + rh * 8;
                red[wn * 128 + nloc] = rowacc[ma * 2 + rh];
            }
    }
    __syncthreads();
    if (tid < 128) {
        float s = red[tid] + red[128 + tid] + red[256 + tid] + red[384 + tid];
        g_partial[(size_t)blockIdx.x * NTOK + n0 + tid] = s;
    }
}

// ---------------- launch ----------------
extern "C" void kernel_launch(void* const* d_in, const int* in_sizes, int n_in,
                              void* d_out, int out_size) {
    const float* features = (const float*)d_in[0];  // [8192, 512]
    const float* w        = (const float*)d_in[1];  // [4096, 8192]
    const float* E        = (const float*)d_in[2];  // [512, 4096]
    const float* b        = (const float*)d_in[3];  // [4096]
    float* out            = (float*)d_out;          // [8192]

    cudaFuncSetAttribute(mm_diag_kernel, cudaFuncAttributeMaxDynamicSharedMemorySize, SMEM_TOTAL);

    conv_f_kernel<<<(NTOK * KDIM + 255) / 256, 256>>>(features);
    conv_e_t_kernel<<<dim3(DDIM / 32, KDIM / 32), dim3(32, 8)>>>(E);
    mm_diag_kernel<<<dim3(DT, NT), 256, SMEM_TOTAL>>>(w, b);
    reduce_kernel<<<(NTOK + 255) / 256, 256>>>(out);
}